// round 1
// baseline (speedup 1.0000x reference)
#include <cuda_runtime.h>

#define NU 100000
#define NV 50000
#define NN 150000
#define DD 64
#define NE 2000000
#define ALPHA (1.0f/3.0f)

#define SCAN_B 256
#define NBLK_SCAN ((NN + SCAN_B - 1) / SCAN_B)   // 586

// ---- device scratch (allocation-free rule: static __device__ globals) ----
__device__ float g_E[NN * DD];     // ego_pos (concat user,item)
__device__ float g_A[NN * DD];     // h1_p (layer-1 pos output)
__device__ float g_B[NN * DD];     // h1_n (layer-1 neg output)
__device__ int   g_cnt_p[NN];
__device__ int   g_cnt_n[NN];
__device__ int   g_off_p[NN];
__device__ int   g_off_n[NN];
__device__ int   g_cur_p[NN];
__device__ int   g_cur_n[NN];
__device__ int   g_src_p[NE];      // CSR-sorted src lists
__device__ int   g_src_n[NE];
__device__ int   g_part_p[1024];
__device__ int   g_part_n[1024];

// ---- K0: materialize ego_pos into g_E (float4), zero counters ----
__global__ void k_init(const float4* __restrict__ ue, const float4* __restrict__ ie) {
    int i = blockIdx.x * blockDim.x + threadIdx.x;          // float4 index
    const int total4 = NN * DD / 4;
    if (i < total4) {
        int g = i * 4;
        int n = g >> 6;             // node
        int c4 = (g & 63) >> 2;     // float4 col within row
        float4 v = (n < NU) ? ue[n * (DD / 4) + c4]
                            : ie[(n - NU) * (DD / 4) + c4];
        reinterpret_cast<float4*>(g_E)[i] = v;
    }
    if (i < NN) { g_cnt_p[i] = 0; g_cnt_n[i] = 0; }
}

// ---- K1: degree histograms for both edge lists ----
__global__ void k_hist(const int* __restrict__ pd, const int* __restrict__ nd) {
    int e = blockIdx.x * blockDim.x + threadIdx.x;
    if (e < NE) {
        atomicAdd(&g_cnt_p[pd[e]], 1);
        atomicAdd(&g_cnt_n[nd[e]], 1);
    }
}

// ---- K2a: per-block exclusive scan of counts, block totals to partials ----
__global__ void k_scan1() {
    __shared__ int s[SCAN_B];
    int list = blockIdx.y;
    const int* cnt = list ? g_cnt_n : g_cnt_p;
    int* off       = list ? g_off_n : g_off_p;
    int* part      = list ? g_part_n : g_part_p;

    int gid = blockIdx.x * SCAN_B + threadIdx.x;
    int v = (gid < NN) ? cnt[gid] : 0;
    int x = v;
    s[threadIdx.x] = x;
    __syncthreads();
    for (int o = 1; o < SCAN_B; o <<= 1) {
        int t = (threadIdx.x >= o) ? s[threadIdx.x - o] : 0;
        __syncthreads();
        x += t;
        s[threadIdx.x] = x;
        __syncthreads();
    }
    if (gid < NN) off[gid] = x - v;                   // block-local exclusive
    if (threadIdx.x == SCAN_B - 1) part[blockIdx.x] = x;   // block total
}

// ---- K2b: exclusive scan of the block partials (one block per list) ----
__global__ void k_scan2(int nblocks) {
    __shared__ int s[1024];
    int* part = blockIdx.x ? g_part_n : g_part_p;
    int t = threadIdx.x;
    s[t] = (t < nblocks) ? part[t] : 0;
    __syncthreads();
    if (t == 0) {
        int run = 0;
        for (int i = 0; i < nblocks; i++) { int v = s[i]; s[i] = run; run += v; }
    }
    __syncthreads();
    if (t < nblocks) part[t] = s[t];
}

// ---- K2c: add block offsets; init fill cursors ----
__global__ void k_scan3() {
    int gid = blockIdx.x * SCAN_B + threadIdx.x;
    if (gid >= NN) return;
    if (blockIdx.y == 0) {
        int o = g_off_p[gid] + g_part_p[gid >> 8];
        g_off_p[gid] = o; g_cur_p[gid] = o;
    } else {
        int o = g_off_n[gid] + g_part_n[gid >> 8];
        g_off_n[gid] = o; g_cur_n[gid] = o;
    }
}

// ---- K3: counting-sort fill of per-dst src lists ----
__global__ void k_fill(const int* __restrict__ ps, const int* __restrict__ pd,
                       const int* __restrict__ ns, const int* __restrict__ nd) {
    int e = blockIdx.x * blockDim.x + threadIdx.x;
    if (e < NE) {
        int s1 = ps[e], d1 = pd[e];
        g_src_p[atomicAdd(&g_cur_p[d1], 1)] = s1;
        int s2 = ns[e], d2 = nd[e];
        g_src_n[atomicAdd(&g_cur_n[d2], 1)] = s2;
    }
}

// gather-reduce helper: warp sums rows of X listed in srclist[start..start+cnt)
// lane holds float2 at column (lane*2). Loop bound uniform across the warp.
__device__ __forceinline__ void gather_accum(const float2* __restrict__ X,
                                             const int* __restrict__ srclist,
                                             int start, int cnt, int lane,
                                             float2& acc) {
    for (int base = 0; base < cnt; base += 32) {
        int rem = cnt - base;
        int m = rem < 32 ? rem : 32;
        int idx = (lane < m) ? srclist[start + base + lane] : 0;
        #pragma unroll 4
        for (int k = 0; k < m; k++) {
            int j = __shfl_sync(0xffffffffu, idx, k);
            float2 v = X[j * 32 + lane];
            acc.x += v.x;
            acc.y += v.y;
        }
    }
}

// ---- K4: layer 1 fused (pos+neg conv, acc init, self-term) ----
// warp per node; out = [pos_acc (NN*DD) | neg_acc (NN*DD)]
__global__ void k_conv1(const float* __restrict__ un, const float* __restrict__ inn,
                        float* __restrict__ out) {
    int warp = (blockIdx.x * blockDim.x + threadIdx.x) >> 5;
    int lane = threadIdx.x & 31;
    if (warp >= NN) return;
    int node = warp;

    const float2* E2 = reinterpret_cast<const float2*>(g_E);
    float2 ego = E2[node * 32 + lane];
    float2 ap = ego, an = ego;   // self term (eps=0 GIN)

    gather_accum(E2, g_src_p, g_off_p[node], g_cnt_p[node], lane, ap);
    gather_accum(E2, g_src_n, g_off_n[node], g_cnt_n[node], lane, an);

    reinterpret_cast<float2*>(g_A)[node * 32 + lane] = ap;
    reinterpret_cast<float2*>(g_B)[node * 32 + lane] = an;

    float2 egon = (node < NU)
        ? reinterpret_cast<const float2*>(un)[node * 32 + lane]
        : reinterpret_cast<const float2*>(inn)[(node - NU) * 32 + lane];

    float2 op, on;
    op.x = ALPHA * (ego.x + ap.x);  op.y = ALPHA * (ego.y + ap.y);
    on.x = ALPHA * (egon.x + an.x); on.y = ALPHA * (egon.y + an.y);
    reinterpret_cast<float2*>(out)[node * 32 + lane] = op;
    reinterpret_cast<float2*>(out + (size_t)NN * DD)[node * 32 + lane] = on;
}

// ---- K5: layer 2 fused (gather from h1, final acc) ----
__global__ void k_conv2(float* __restrict__ out) {
    int warp = (blockIdx.x * blockDim.x + threadIdx.x) >> 5;
    int lane = threadIdx.x & 31;
    if (warp >= NN) return;
    int node = warp;

    const float2* A2 = reinterpret_cast<const float2*>(g_A);
    const float2* B2 = reinterpret_cast<const float2*>(g_B);

    float2 ap = A2[node * 32 + lane];
    float2 an = B2[node * 32 + lane];

    gather_accum(A2, g_src_p, g_off_p[node], g_cnt_p[node], lane, ap);
    gather_accum(B2, g_src_n, g_off_n[node], g_cnt_n[node], lane, an);

    float2* outp = reinterpret_cast<float2*>(out);
    float2* outn = reinterpret_cast<float2*>(out + (size_t)NN * DD);
    float2 pp = outp[node * 32 + lane];
    float2 pn = outn[node * 32 + lane];
    pp.x += ALPHA * ap.x;  pp.y += ALPHA * ap.y;
    pn.x += ALPHA * an.x;  pn.y += ALPHA * an.y;
    outp[node * 32 + lane] = pp;
    outn[node * 32 + lane] = pn;
}

extern "C" void kernel_launch(void* const* d_in, const int* in_sizes, int n_in,
                              void* d_out, int out_size) {
    const float* ue  = (const float*)d_in[0];   // user_embedding     [NU,64]
    const float* ie  = (const float*)d_in[1];   // item_embedding     [NV,64]
    const float* un  = (const float*)d_in[2];   // user_neg_embedding [NU,64]
    const float* inn = (const float*)d_in[3];   // item_neg_embedding [NV,64]
    const int* pe    = (const int*)d_in[4];     // pos_edges [2,NE]: row0 src, row1 dst
    const int* ne    = (const int*)d_in[5];     // neg_edges [2,NE]
    float* out = (float*)d_out;

    const int* ps = pe;        const int* pd = pe + NE;
    const int* ns = ne;        const int* nd = ne + NE;

    // K0: ego copy + zero counters
    {
        int total4 = NN * DD / 4;
        int blk = (total4 + 255) / 256;
        k_init<<<blk, 256>>>((const float4*)ue, (const float4*)ie);
    }
    // K1: histogram
    k_hist<<<(NE + 255) / 256, 256>>>(pd, nd);
    // K2: two-level exclusive scan
    {
        dim3 g1(NBLK_SCAN, 2);
        k_scan1<<<g1, SCAN_B>>>();
        k_scan2<<<2, 1024>>>(NBLK_SCAN);
        k_scan3<<<g1, SCAN_B>>>();
    }
    // K3: fill CSR src lists
    k_fill<<<(NE + 255) / 256, 256>>>(ps, pd, ns, nd);

    // K4/K5: fused conv layers (warp per node, 8 warps per block)
    int conv_blocks = NN / 8;   // 150000 / 8 = 18750 exactly
    k_conv1<<<conv_blocks, 256>>>(un, inn, out);
    k_conv2<<<conv_blocks, 256>>>(out);
}